// round 12
// baseline (speedup 1.0000x reference)
#include <cuda_runtime.h>
#include <cuda_bf16.h>
#include <float.h>

// Problem constants
#define NUMS 512
#define DIM  1024
#define BT   32768            // B*T = 16*2048 rows
#define TOPK 33               // 512//16 + 1

// Scratch (allocation-free rule: __device__ globals).
// IMPORTANT: only referenced from DEVICE code (host-side symbol decay is garbage).
__device__ float g_att[(size_t)BT * NUMS];   // 64 MB attention buffer
__device__ float g_mt[(size_t)DIM * NUMS];   // 2 MB transposed memory_block [d][k]

// ---------------------------------------------------------------------------
// Packed f32x2 helpers (Blackwell sm_103a: FFMA2 via PTX fma.rn.f32x2)
// ---------------------------------------------------------------------------
__device__ __forceinline__ unsigned long long pack2(float lo, float hi)
{
    unsigned long long r;
    asm("mov.b64 %0, {%1, %2};"
        : "=l"(r) : "r"(__float_as_uint(lo)), "r"(__float_as_uint(hi)));
    return r;
}

__device__ __forceinline__ float2 unpack2(unsigned long long v)
{
    unsigned lo, hi;
    asm("mov.b64 {%0, %1}, %2;" : "=r"(lo), "=r"(hi) : "l"(v));
    return make_float2(__uint_as_float(lo), __uint_as_float(hi));
}

#define FFMA2(d, a, b) \
    asm("fma.rn.f32x2 %0, %1, %2, %0;" : "+l"(d) : "l"(a), "l"(b))

// ---------------------------------------------------------------------------
// Transpose memory_block [NUMS][DIM] -> g_mt [DIM][NUMS]
// ---------------------------------------------------------------------------
__global__ void transpose_kernel(const float* __restrict__ src)
{
    __shared__ float tile[32][33];
    int d0 = blockIdx.x * 32;   // column (DIM) tile
    int k0 = blockIdx.y * 32;   // row (NUMS) tile
    int x = threadIdx.x;        // 0..31
    int y = threadIdx.y;        // 0..7
#pragma unroll
    for (int j = 0; j < 32; j += 8)
        tile[y + j][x] = src[(size_t)(k0 + y + j) * DIM + d0 + x];
    __syncthreads();
#pragma unroll
    for (int j = 0; j < 32; j += 8)
        g_mt[(size_t)(d0 + y + j) * NUMS + k0 + x] = tile[x][y + j];
}

// ---------------------------------------------------------------------------
// SGEMM: C[M,N] = A[M,K] (row-major) * B[K,N] (row-major)
// CTA tile 128x128, BK=8, 256 threads, 8x8 per thread, smem double-buffered.
// Inner product uses packed fma.rn.f32x2 (2 fp32 FMA per issue slot).
// MODE selects operand binding IN DEVICE CODE (globals must not cross the
// host/device boundary as kernel args):
//   MODE=1 (GEMM1): A=param(data), B=g_mt,       C=g_att, sigmoid epilogue
//   MODE=2 (GEMM2): A=g_att,       B=param(mem), C=param(out)
// All dims are multiples of tile sizes for this problem (no bounds checks).
// ---------------------------------------------------------------------------
#define BM 128
#define BN 128
#define BK 8
#define TM 8
#define TN 8

template <int MODE>
__global__ __launch_bounds__(256, 2)
void sgemm_kernel(const float* __restrict__ Ap, const float* __restrict__ Bp,
                  float* __restrict__ Cp, int M, int N, int K)
{
    constexpr bool SIGMOID = (MODE == 1);
    const float* __restrict__ A = (MODE == 1) ? Ap : (const float*)g_att;
    const float* __restrict__ B = (MODE == 1) ? (const float*)g_mt : Bp;
    float* __restrict__       C = (MODE == 1) ? (float*)g_att : Cp;

    __shared__ float As[2][BK][BM + 4];   // +4 pad kills store bank conflicts
    __shared__ float Bs[2][BK][BN];

    const int tid  = threadIdx.x;
    const int bRow = blockIdx.y * BM;
    const int bCol = blockIdx.x * BN;

    // compute-thread mapping: 16x16 thread grid, 8x8 register tile each
    const int tx = tid & 15;        // col group
    const int ty = tid >> 4;        // row group

    // load mapping
    const int aRow  = tid >> 1;            // 0..127
    const int aK    = (tid & 1) * 4;       // 0 or 4
    const int bK    = tid >> 5;            // 0..7
    const int bCol4 = (tid & 31) * 4;      // 0..124

    const float* Aptr = A + (size_t)(bRow + aRow) * K + aK;
    const float* Bptr = B + (size_t)bK * N + bCol + bCol4;

    // packed accumulators: acc2[i][j2] = {C[i][2*j2], C[i][2*j2+1]}
    unsigned long long acc2[TM][TN / 2];
#pragma unroll
    for (int i = 0; i < TM; ++i)
#pragma unroll
        for (int j = 0; j < TN / 2; ++j) acc2[i][j] = 0ull;   // {0.0f, 0.0f}

    // preload tile 0 into buffer 0
    float4 a4 = *(const float4*)(Aptr);
    float4 b4 = *(const float4*)(Bptr);
    As[0][aK + 0][aRow] = a4.x;
    As[0][aK + 1][aRow] = a4.y;
    As[0][aK + 2][aRow] = a4.z;
    As[0][aK + 3][aRow] = a4.w;
    *(float4*)&Bs[0][bK][bCol4] = b4;
    __syncthreads();

    const int nTiles = K / BK;
    float ar[TM], br[TN];

    for (int t = 1; t < nTiles; ++t) {
        // prefetch next tile into registers
        a4 = *(const float4*)(Aptr + t * BK);
        b4 = *(const float4*)(Bptr + (size_t)t * BK * N);

        const int cur = (t - 1) & 1;
#pragma unroll
        for (int k = 0; k < BK; ++k) {
            *(float4*)&ar[0] = *(const float4*)&As[cur][k][ty * TM];
            *(float4*)&ar[4] = *(const float4*)&As[cur][k][ty * TM + 4];
            *(float4*)&br[0] = *(const float4*)&Bs[cur][k][tx * TN];
            *(float4*)&br[4] = *(const float4*)&Bs[cur][k][tx * TN + 4];

            unsigned long long bp[TN / 2];
#pragma unroll
            for (int j = 0; j < TN / 2; ++j) bp[j] = pack2(br[2 * j], br[2 * j + 1]);
#pragma unroll
            for (int i = 0; i < TM; ++i) {
                unsigned long long ap = pack2(ar[i], ar[i]);
#pragma unroll
                for (int j = 0; j < TN / 2; ++j) FFMA2(acc2[i][j], ap, bp[j]);
            }
        }

        const int nxt = t & 1;
        As[nxt][aK + 0][aRow] = a4.x;
        As[nxt][aK + 1][aRow] = a4.y;
        As[nxt][aK + 2][aRow] = a4.z;
        As[nxt][aK + 3][aRow] = a4.w;
        *(float4*)&Bs[nxt][bK][bCol4] = b4;
        __syncthreads();
    }

    // last tile
    {
        const int cur = (nTiles - 1) & 1;
#pragma unroll
        for (int k = 0; k < BK; ++k) {
            *(float4*)&ar[0] = *(const float4*)&As[cur][k][ty * TM];
            *(float4*)&ar[4] = *(const float4*)&As[cur][k][ty * TM + 4];
            *(float4*)&br[0] = *(const float4*)&Bs[cur][k][tx * TN];
            *(float4*)&br[4] = *(const float4*)&Bs[cur][k][tx * TN + 4];

            unsigned long long bp[TN / 2];
#pragma unroll
            for (int j = 0; j < TN / 2; ++j) bp[j] = pack2(br[2 * j], br[2 * j + 1]);
#pragma unroll
            for (int i = 0; i < TM; ++i) {
                unsigned long long ap = pack2(ar[i], ar[i]);
#pragma unroll
                for (int j = 0; j < TN / 2; ++j) FFMA2(acc2[i][j], ap, bp[j]);
            }
        }
    }

    // epilogue
#pragma unroll
    for (int i = 0; i < TM; ++i) {
        float* Crow = C + (size_t)(bRow + ty * TM + i) * N + bCol + tx * TN;
#pragma unroll
        for (int j4 = 0; j4 < TN; j4 += 4) {
            float2 p0 = unpack2(acc2[i][j4 / 2]);
            float2 p1 = unpack2(acc2[i][j4 / 2 + 1]);
            float4 v;
            if (SIGMOID) {
                v.x = 1.0f / (1.0f + __expf(-p0.x * 0.03125f));
                v.y = 1.0f / (1.0f + __expf(-p0.y * 0.03125f));
                v.z = 1.0f / (1.0f + __expf(-p1.x * 0.03125f));
                v.w = 1.0f / (1.0f + __expf(-p1.y * 0.03125f));
            } else {
                v.x = p0.x; v.y = p0.y; v.z = p1.x; v.w = p1.y;
            }
            *(float4*)(Crow + j4) = v;
        }
    }
}

// ---------------------------------------------------------------------------
// Top-33 mean per row: one warp per row of attention [BT][NUMS]
// ---------------------------------------------------------------------------
__global__ void topk_kernel(float* __restrict__ out)
{
    const int warp = (blockIdx.x * blockDim.x + threadIdx.x) >> 5;
    const int lane = threadIdx.x & 31;
    if (warp >= BT) return;

    const float* __restrict__ row = g_att + (size_t)warp * NUMS;
    float v[NUMS / 32];
#pragma unroll
    for (int j = 0; j < NUMS / 32; ++j)
        v[j] = row[lane + j * 32];

    float sum = 0.0f;
    for (int it = 0; it < TOPK; ++it) {
        float lm = -FLT_MAX;
        int   li = 0;
#pragma unroll
        for (int j = 0; j < NUMS / 32; ++j)
            if (v[j] > lm) { lm = v[j]; li = j; }

        float m = lm;
#pragma unroll
        for (int off = 16; off > 0; off >>= 1)
            m = fmaxf(m, __shfl_xor_sync(0xffffffffu, m, off));
        sum += m;

        unsigned bal = __ballot_sync(0xffffffffu, lm == m);
        if (lane == (__ffs(bal) - 1)) v[li] = -FLT_MAX;
    }
    if (lane == 0) out[warp] = sum * (1.0f / (float)TOPK);
}

// ---------------------------------------------------------------------------
// kernel_launch: transpose -> GEMM1(+sigmoid) -> topk -> GEMM2
// Output packing: [0, 32768) = temporal_att, [32768, ...) = augment
// NOTE: no __device__ symbol is ever passed as a kernel argument from host
// code — globals are bound inside device code via the MODE template param.
// ---------------------------------------------------------------------------
extern "C" void kernel_launch(void* const* d_in, const int* in_sizes, int n_in,
                              void* d_out, int out_size)
{
    const float* data = (const float*)d_in[0];   // [16,2048,1024]
    const float* mem  = (const float*)d_in[1];   // [512,1024]
    float* out = (float*)d_out;

    // 1) transpose memory_block -> g_mt [DIM][NUMS]
    transpose_kernel<<<dim3(DIM / 32, NUMS / 32), dim3(32, 8)>>>(mem);

    // 2) attention = sigmoid(data @ mem^T / 32) -> g_att
    sgemm_kernel<1><<<dim3(NUMS / BN, BT / BM), 256>>>(data, nullptr, nullptr, BT, NUMS, DIM);

    // 3) temporal_att = mean(top33(attention))
    topk_kernel<<<BT / 8, 256>>>(out);

    // 4) augment = attention @ mem
    sgemm_kernel<2><<<dim3(DIM / BN, BT / BM), 256>>>(nullptr, mem, out + BT, BT, DIM, NUMS);
}

// round 17
// speedup vs baseline: 2.3923x; 2.3923x over previous
#include <cuda_runtime.h>
#include <cuda_bf16.h>
#include <float.h>
#include <stdint.h>

#define NUMS 512
#define DIM  1024
#define BT   32768
#define TOPK 33

// __device__ scratch (allocation-free rule). DEVICE-code references only.
__device__ float         g_att[(size_t)BT * NUMS];        // fp32 attention
__device__ __nv_bfloat16 g_data_bf16[(size_t)BT * DIM];
__device__ __nv_bfloat16 g_mem_bf16[(size_t)NUMS * DIM];

// ---------------------------------------------------------------------------
// helpers
// ---------------------------------------------------------------------------
__device__ __forceinline__ uint32_t smem_u32(const void* p)
{
    uint32_t a;
    asm("{ .reg .u64 t; cvta.to.shared.u64 t, %1; cvt.u32.u64 %0, t; }" : "=r"(a) : "l"(p));
    return a;
}

#define SWZ128(off) ((off) ^ (((off) >> 3) & 0x70))

__device__ __forceinline__ void ldmx4(uint32_t* r, uint32_t addr)
{
    asm volatile("ldmatrix.sync.aligned.m8n8.x4.shared.b16 {%0,%1,%2,%3}, [%4];"
                 : "=r"(r[0]), "=r"(r[1]), "=r"(r[2]), "=r"(r[3]) : "r"(addr));
}

__device__ __forceinline__ void mma_bf16(float* d, const uint32_t* a, const uint32_t* b)
{
    asm volatile("mma.sync.aligned.m16n8k16.row.col.f32.bf16.bf16.f32 "
                 "{%0,%1,%2,%3},{%4,%5,%6,%7},{%8,%9},{%0,%1,%2,%3};"
                 : "+f"(d[0]), "+f"(d[1]), "+f"(d[2]), "+f"(d[3])
                 : "r"(a[0]), "r"(a[1]), "r"(a[2]), "r"(a[3]), "r"(b[0]), "r"(b[1]));
}

__device__ __forceinline__ void mma_tf32(float* d, const uint32_t* a, const uint32_t* b)
{
    asm volatile("mma.sync.aligned.m16n8k8.row.col.f32.tf32.tf32.f32 "
                 "{%0,%1,%2,%3},{%4,%5,%6,%7},{%8,%9},{%0,%1,%2,%3};"
                 : "+f"(d[0]), "+f"(d[1]), "+f"(d[2]), "+f"(d[3])
                 : "r"(a[0]), "r"(a[1]), "r"(a[2]), "r"(a[3]), "r"(b[0]), "r"(b[1]));
}

__device__ __forceinline__ uint32_t f2tf32(float f)
{
    uint32_t u;
    asm("cvt.rna.tf32.f32 %0, %1;" : "=r"(u) : "f"(f));
    return u;
}

__device__ __forceinline__ float sigmf(float x)
{
    return 1.0f / (1.0f + __expf(-x * 0.03125f));
}

// ---------------------------------------------------------------------------
// fp32 -> bf16 conversion prepasses
// ---------------------------------------------------------------------------
__global__ void convert_data_kernel(const float* __restrict__ src)
{
    size_t i = ((size_t)blockIdx.x * blockDim.x + threadIdx.x) * 4;
    float4 v = *(const float4*)(src + i);
    __nv_bfloat162 a = __float22bfloat162_rn(make_float2(v.x, v.y));
    __nv_bfloat162 b = __float22bfloat162_rn(make_float2(v.z, v.w));
    uint2 pk; pk.x = *(uint32_t*)&a; pk.y = *(uint32_t*)&b;
    *(uint2*)(g_data_bf16 + i) = pk;
}

__global__ void convert_mem_kernel(const float* __restrict__ src)
{
    size_t i = ((size_t)blockIdx.x * blockDim.x + threadIdx.x) * 4;
    float4 v = *(const float4*)(src + i);
    __nv_bfloat162 a = __float22bfloat162_rn(make_float2(v.x, v.y));
    __nv_bfloat162 b = __float22bfloat162_rn(make_float2(v.z, v.w));
    uint2 pk; pk.x = *(uint32_t*)&a; pk.y = *(uint32_t*)&b;
    *(uint2*)(g_mem_bf16 + i) = pk;
}

// ---------------------------------------------------------------------------
// GEMM1 (bf16 mma.sync): attention = sigmoid(data @ mem^T / 32) -> g_att
// CTA 128x128, 8 warps (4M x 2N), warp tile 32x64. K chunk 64 bf16 (SW128 rows).
// ---------------------------------------------------------------------------
__global__ void __launch_bounds__(256) gemm1_mma()
{
    __shared__ __align__(1024) uint8_t smA[16384];   // 128 rows x 64 bf16 (128B, SW128)
    __shared__ __align__(1024) uint8_t smB[16384];

    const int tid = threadIdx.x, lane = tid & 31, wid = tid >> 5;
    const int wm = wid & 3, wn = wid >> 2;
    const int bRow = blockIdx.y * 128, bCol = blockIdx.x * 128;
    const uint32_t sA = smem_u32(smA), sB = smem_u32(smB);

    float acc[2][8][4];
#pragma unroll
    for (int mi = 0; mi < 2; ++mi)
#pragma unroll
        for (int ni = 0; ni < 8; ++ni)
#pragma unroll
            for (int e = 0; e < 4; ++e) acc[mi][ni][e] = 0.0f;

    for (int kc = 0; kc < 16; ++kc) {
#pragma unroll
        for (int i = 0; i < 4; ++i) {
            int idx = tid + i * 256;                // 0..1023
            int row = idx >> 3, c = idx & 7;        // 16B column
            uint32_t sw = SWZ128((uint32_t)(row * 128 + c * 16));
            *(uint4*)(smA + sw) = *(const uint4*)(g_data_bf16 + (size_t)(bRow + row) * DIM + kc * 64 + c * 8);
            *(uint4*)(smB + sw) = *(const uint4*)(g_mem_bf16  + (size_t)(bCol + row) * DIM + kc * 64 + c * 8);
        }
        __syncthreads();

#pragma unroll
        for (int ks = 0; ks < 4; ++ks) {            // 4 x k16
            uint32_t a[2][4];
#pragma unroll
            for (int mi = 0; mi < 2; ++mi) {
                int row = wm * 32 + mi * 16 + (lane & 15);
                uint32_t off = (uint32_t)(row * 128 + ks * 32 + (lane >> 4) * 16);
                ldmx4(a[mi], sA + SWZ128(off));
            }
            uint32_t b[8][2];
#pragma unroll
            for (int ng = 0; ng < 4; ++ng) {        // n16 group
                int n = wn * 64 + ng * 16 + (lane & 7) + ((lane >> 4) << 3);
                uint32_t off = (uint32_t)(n * 128 + ks * 32 + ((lane >> 3) & 1) * 16);
                uint32_t r[4];
                ldmx4(r, sB + SWZ128(off));
                b[ng * 2][0] = r[0]; b[ng * 2][1] = r[1];
                b[ng * 2 + 1][0] = r[2]; b[ng * 2 + 1][1] = r[3];
            }
#pragma unroll
            for (int mi = 0; mi < 2; ++mi)
#pragma unroll
                for (int ni = 0; ni < 8; ++ni)
                    mma_bf16(acc[mi][ni], a[mi], b[ni]);
        }
        __syncthreads();
    }

    // epilogue: sigmoid -> g_att
#pragma unroll
    for (int mi = 0; mi < 2; ++mi) {
        int r0 = bRow + wm * 32 + mi * 16 + (lane >> 2);
#pragma unroll
        for (int ni = 0; ni < 8; ++ni) {
            int c0 = bCol + wn * 64 + ni * 8 + (lane & 3) * 2;
            float* p = g_att + (size_t)r0 * NUMS + c0;
            p[0] = sigmf(acc[mi][ni][0]);
            p[1] = sigmf(acc[mi][ni][1]);
            float* q = g_att + (size_t)(r0 + 8) * NUMS + c0;
            q[0] = sigmf(acc[mi][ni][2]);
            q[1] = sigmf(acc[mi][ni][3]);
        }
    }
}

// ---------------------------------------------------------------------------
// GEMM2 (tf32 mma.sync): augment = g_att[BT,512] @ mem[512,1024] -> out
// CTA 128x128, warp tile 32x64. K chunk 32 fp32. mem[k][n] is col-major KxN.
// ---------------------------------------------------------------------------
__global__ void __launch_bounds__(256) gemm2_mma(const float* __restrict__ Bmem,
                                                float* __restrict__ Cout)
{
    __shared__ float smA[128 * 36];   // [m][k] pad 36 -> conflict-free frags
    __shared__ float smB[32 * 132];   // [k][n] pad 132

    const int tid = threadIdx.x, lane = tid & 31, wid = tid >> 5;
    const int wm = wid & 3, wn = wid >> 2;
    const int bRow = blockIdx.y * 128, bCol = blockIdx.x * 128;

    float acc[2][8][4];
#pragma unroll
    for (int mi = 0; mi < 2; ++mi)
#pragma unroll
        for (int ni = 0; ni < 8; ++ni)
#pragma unroll
            for (int e = 0; e < 4; ++e) acc[mi][ni][e] = 0.0f;

    for (int kc = 0; kc < 16; ++kc) {
#pragma unroll
        for (int i = 0; i < 4; ++i) {
            int idx = tid + i * 256;                // 0..1023
            int m = idx >> 3, k4 = (idx & 7) * 4;
            *(float4*)&smA[m * 36 + k4] =
                *(const float4*)(g_att + (size_t)(bRow + m) * NUMS + kc * 32 + k4);
            int k = idx >> 5, n4 = (idx & 31) * 4;
            *(float4*)&smB[k * 132 + n4] =
                *(const float4*)(Bmem + (size_t)(kc * 32 + k) * DIM + bCol + n4);
        }
        __syncthreads();

#pragma unroll
        for (int ks = 0; ks < 4; ++ks) {            // 4 x k8
            const int kb = ks * 8;
            uint32_t a[2][4];
#pragma unroll
            for (int mi = 0; mi < 2; ++mi) {
                int r = wm * 32 + mi * 16 + (lane >> 2);
                int c = kb + (lane & 3);
                a[mi][0] = f2tf32(smA[r * 36 + c]);
                a[mi][1] = f2tf32(smA[(r + 8) * 36 + c]);
                a[mi][2] = f2tf32(smA[r * 36 + c + 4]);
                a[mi][3] = f2tf32(smA[(r + 8) * 36 + c + 4]);
            }
            uint32_t b[8][2];
#pragma unroll
            for (int ni = 0; ni < 8; ++ni) {
                int n = wn * 64 + ni * 8 + (lane >> 2);
                int k = kb + (lane & 3);
                b[ni][0] = f2tf32(smB[k * 132 + n]);
                b[ni][1] = f2tf32(smB[(k + 4) * 132 + n]);
            }
#pragma unroll
            for (int mi = 0; mi < 2; ++mi)
#pragma unroll
                for (int ni = 0; ni < 8; ++ni)
                    mma_tf32(acc[mi][ni], a[mi], b[ni]);
        }
        __syncthreads();
    }

#pragma unroll
    for (int mi = 0; mi < 2; ++mi) {
        int r0 = bRow + wm * 32 + mi * 16 + (lane >> 2);
#pragma unroll
        for (int ni = 0; ni < 8; ++ni) {
            int c0 = bCol + wn * 64 + ni * 8 + (lane & 3) * 2;
            float* p = Cout + (size_t)r0 * DIM + c0;
            p[0] = acc[mi][ni][0];
            p[1] = acc[mi][ni][1];
            float* q = Cout + (size_t)(r0 + 8) * DIM + c0;
            q[0] = acc[mi][ni][2];
            q[1] = acc[mi][ni][3];
        }
    }
}

// ---------------------------------------------------------------------------
// Top-33 mean per row (unchanged)
// ---------------------------------------------------------------------------
__global__ void topk_kernel(float* __restrict__ out)
{
    const int warp = (blockIdx.x * blockDim.x + threadIdx.x) >> 5;
    const int lane = threadIdx.x & 31;
    if (warp >= BT) return;

    const float* __restrict__ row = g_att + (size_t)warp * NUMS;
    float v[NUMS / 32];
#pragma unroll
    for (int j = 0; j < NUMS / 32; ++j)
        v[j] = row[lane + j * 32];

    float sum = 0.0f;
    for (int it = 0; it < TOPK; ++it) {
        float lm = -FLT_MAX;
        int   li = 0;
#pragma unroll
        for (int j = 0; j < NUMS / 32; ++j)
            if (v[j] > lm) { lm = v[j]; li = j; }
        float m = lm;
#pragma unroll
        for (int off = 16; off > 0; off >>= 1)
            m = fmaxf(m, __shfl_xor_sync(0xffffffffu, m, off));
        sum += m;
        unsigned bal = __ballot_sync(0xffffffffu, lm == m);
        if (lane == (__ffs(bal) - 1)) v[li] = -FLT_MAX;
    }
    if (lane == 0) out[warp] = sum * (1.0f / (float)TOPK);
}

// ---------------------------------------------------------------------------
// kernel_launch: convert -> GEMM1(bf16 mma + sigmoid) -> topk -> GEMM2(tf32 mma)
// Output packing: [0, 32768) = temporal_att, [32768, ...) = augment
// ---------------------------------------------------------------------------
extern "C" void kernel_launch(void* const* d_in, const int* in_sizes, int n_in,
                              void* d_out, int out_size)
{
    const float* data = (const float*)d_in[0];   // [16,2048,1024]
    const float* mem  = (const float*)d_in[1];   // [512,1024]
    float* out = (float*)d_out;

    convert_data_kernel<<<(BT * DIM) / 4 / 256, 256>>>(data);
    convert_mem_kernel<<<(NUMS * DIM) / 4 / 256, 256>>>(mem);

    gemm1_mma<<<dim3(NUMS / 128, BT / 128), 256>>>();

    topk_kernel<<<BT / 8, 256>>>(out);

    gemm2_mma<<<dim3(DIM / 128, BT / 128), 256>>>(mem, out + BT);
}